// round 2
// baseline (speedup 1.0000x reference)
#include <cuda_runtime.h>
#include <math.h>

// Problem constants
#define BB   4
#define SS   2048
#define DD   1024
#define HH   16
#define DK   64
#define MTOT (BB * SS)   // 8192

// Scratch (device globals; no runtime allocation allowed)
__device__ float g_q[(size_t)MTOT * DD];
__device__ float g_k[(size_t)MTOT * DD];
__device__ float g_v[(size_t)MTOT * DD];
__device__ float g_ctx[(size_t)MTOT * DD];

// ---------------------------------------------------------------------------
// GEMM: C[M,N] = A[M,K] * B[N,K]^T   (both A and B row-major, K contiguous)
// Tile: BM=64, BN=64, BK=16, 256 threads, 4x4 register microtile per thread.
// ---------------------------------------------------------------------------
__global__ __launch_bounds__(256) void gemm_abt(
    const float* __restrict__ A, const float* __restrict__ B,
    float* __restrict__ C, int M, int N, int K)
{
    __shared__ float As[64][17];
    __shared__ float Bs[64][17];

    const int tid = threadIdx.x;
    const int tx = tid & 15;       // 0..15 -> N microtile
    const int ty = tid >> 4;       // 0..15 -> M microtile
    const int row0 = blockIdx.y * 64;
    const int col0 = blockIdx.x * 64;

    // cooperative load mapping: each thread loads one float4 of A and B per BK step
    const int lr = tid >> 2;        // 0..63 row within tile
    const int lk = (tid & 3) * 4;   // 0,4,8,12 k offset

    const float* Ap = A + (size_t)(row0 + lr) * K + lk;
    const float* Bp = B + (size_t)(col0 + lr) * K + lk;

    float acc[4][4];
#pragma unroll
    for (int i = 0; i < 4; i++)
#pragma unroll
        for (int j = 0; j < 4; j++) acc[i][j] = 0.0f;

    for (int kt = 0; kt < K; kt += 16) {
        float4 av = *(const float4*)(Ap + kt);
        float4 bv = *(const float4*)(Bp + kt);
        As[lr][lk + 0] = av.x; As[lr][lk + 1] = av.y;
        As[lr][lk + 2] = av.z; As[lr][lk + 3] = av.w;
        Bs[lr][lk + 0] = bv.x; Bs[lr][lk + 1] = bv.y;
        Bs[lr][lk + 2] = bv.z; Bs[lr][lk + 3] = bv.w;
        __syncthreads();

#pragma unroll
        for (int kk = 0; kk < 16; kk++) {
            float a[4], b[4];
#pragma unroll
            for (int i = 0; i < 4; i++) a[i] = As[4 * ty + i][kk];
#pragma unroll
            for (int j = 0; j < 4; j++) b[j] = Bs[4 * tx + j][kk];
#pragma unroll
            for (int i = 0; i < 4; i++)
#pragma unroll
                for (int j = 0; j < 4; j++) acc[i][j] += a[i] * b[j];
        }
        __syncthreads();
    }

#pragma unroll
    for (int i = 0; i < 4; i++) {
        float* Cp = C + (size_t)(row0 + 4 * ty + i) * N + col0 + 4 * tx;
#pragma unroll
        for (int j = 0; j < 4; j++) Cp[j] = acc[i][j];
    }
}

// ---------------------------------------------------------------------------
// Flash attention over head-separated layout.
// q,k,v,ctx are [B*S, D] with head h occupying columns [h*64, h*64+64).
// Grid: (S/64, H, B). 256 threads. BM=BN=64, DK=64.
// Q tile pre-scaled by 1/sqrt(DK). Online softmax; P overwrites K smem tile.
// ---------------------------------------------------------------------------
__global__ __launch_bounds__(256) void attn_kernel(
    const float* __restrict__ q, const float* __restrict__ k,
    const float* __restrict__ v, float* __restrict__ ctx)
{
    extern __shared__ float sm[];
    float* Qs = sm;                 // 64 x 65 (padded)
    float* Ks = Qs + 64 * 65;       // 64 x 65 (padded), aliased as P after S computed
    float* Vs = Ks + 64 * 65;       // 64 x 64 (unpadded, float4-aligned rows)

    const int tid = threadIdx.x;
    const int tx = tid & 15;
    const int ty = tid >> 4;
    const int b = blockIdx.z;
    const int h = blockIdx.y;
    const int q0 = blockIdx.x * 64;

    const float* qp = q + ((size_t)(b * SS) + q0) * DD + h * DK;
    const float* kp = k + (size_t)(b * SS) * DD + h * DK;
    const float* vp = v + (size_t)(b * SS) * DD + h * DK;

    // load Q tile (scaled by 1/sqrt(64) = 0.125)
#pragma unroll
    for (int c = 0; c < 4; c++) {
        int idx = tid + c * 256;        // 0..1023 float4 slots (64 rows x 16)
        int r = idx >> 4;
        int c4 = (idx & 15) * 4;
        float4 val = *(const float4*)(qp + (size_t)r * DD + c4);
        Qs[r * 65 + c4 + 0] = val.x * 0.125f;
        Qs[r * 65 + c4 + 1] = val.y * 0.125f;
        Qs[r * 65 + c4 + 2] = val.z * 0.125f;
        Qs[r * 65 + c4 + 3] = val.w * 0.125f;
    }

    float m_i[4], l_i[4], acc[4][4];
#pragma unroll
    for (int i = 0; i < 4; i++) {
        m_i[i] = -1e30f;
        l_i[i] = 0.0f;
#pragma unroll
        for (int j = 0; j < 4; j++) acc[i][j] = 0.0f;
    }

    for (int kt = 0; kt < SS; kt += 64) {
        // load K and V tiles
#pragma unroll
        for (int c = 0; c < 4; c++) {
            int idx = tid + c * 256;
            int r = idx >> 4;
            int c4 = (idx & 15) * 4;
            float4 kv = *(const float4*)(kp + (size_t)(kt + r) * DD + c4);
            Ks[r * 65 + c4 + 0] = kv.x;
            Ks[r * 65 + c4 + 1] = kv.y;
            Ks[r * 65 + c4 + 2] = kv.z;
            Ks[r * 65 + c4 + 3] = kv.w;
            float4 vv = *(const float4*)(vp + (size_t)(kt + r) * DD + c4);
            *(float4*)(&Vs[r * 64 + c4]) = vv;
        }
        __syncthreads();

        // S = Q * K^T  (per-thread 4x4 microtile)
        float s[4][4];
#pragma unroll
        for (int i = 0; i < 4; i++)
#pragma unroll
            for (int j = 0; j < 4; j++) s[i][j] = 0.0f;

#pragma unroll 16
        for (int kk = 0; kk < 64; kk++) {
            float a[4], bb[4];
#pragma unroll
            for (int i = 0; i < 4; i++) a[i] = Qs[(4 * ty + i) * 65 + kk];
#pragma unroll
            for (int j = 0; j < 4; j++) bb[j] = Ks[(4 * tx + j) * 65 + kk];
#pragma unroll
            for (int i = 0; i < 4; i++)
#pragma unroll
                for (int j = 0; j < 4; j++) s[i][j] += a[i] * bb[j];
        }

        // online softmax per row (16 lanes per row share via shfl, width-16 groups)
        float alpha[4];
#pragma unroll
        for (int i = 0; i < 4; i++) {
            float rmax = s[i][0];
#pragma unroll
            for (int j = 1; j < 4; j++) rmax = fmaxf(rmax, s[i][j]);
#pragma unroll
            for (int off = 8; off >= 1; off >>= 1)
                rmax = fmaxf(rmax, __shfl_xor_sync(0xffffffffu, rmax, off));
            float m_new = fmaxf(m_i[i], rmax);
            alpha[i] = __expf(m_i[i] - m_new);
            m_i[i] = m_new;
            float rsum = 0.0f;
#pragma unroll
            for (int j = 0; j < 4; j++) {
                s[i][j] = __expf(s[i][j] - m_new);
                rsum += s[i][j];
            }
#pragma unroll
            for (int off = 8; off >= 1; off >>= 1)
                rsum += __shfl_xor_sync(0xffffffffu, rsum, off);
            l_i[i] = l_i[i] * alpha[i] + rsum;
#pragma unroll
            for (int j = 0; j < 4; j++) acc[i][j] *= alpha[i];
        }

        __syncthreads();   // all threads done reading Ks

        // write P into Ks region
#pragma unroll
        for (int i = 0; i < 4; i++)
#pragma unroll
            for (int j = 0; j < 4; j++)
                Ks[(4 * ty + i) * 65 + 4 * tx + j] = s[i][j];
        __syncthreads();

        // O += P * V
#pragma unroll 16
        for (int kk = 0; kk < 64; kk++) {
            float a[4], bb[4];
#pragma unroll
            for (int i = 0; i < 4; i++) a[i] = Ks[(4 * ty + i) * 65 + kk];
#pragma unroll
            for (int j = 0; j < 4; j++) bb[j] = Vs[kk * 64 + 4 * tx + j];
#pragma unroll
            for (int i = 0; i < 4; i++)
#pragma unroll
                for (int j = 0; j < 4; j++) acc[i][j] += a[i] * bb[j];
        }
        __syncthreads();
    }

    // normalize and write out (ctx is [B*S, D] layout, head h columns)
    float* op = ctx + ((size_t)(b * SS) + q0) * DD + h * DK;
#pragma unroll
    for (int i = 0; i < 4; i++) {
        float inv_l = 1.0f / l_i[i];
#pragma unroll
        for (int j = 0; j < 4; j++)
            op[(size_t)(4 * ty + i) * DD + 4 * tx + j] = acc[i][j] * inv_l;
    }
}

// ---------------------------------------------------------------------------
// Launch
// ---------------------------------------------------------------------------
extern "C" void kernel_launch(void* const* d_in, const int* in_sizes, int n_in,
                              void* d_out, int out_size)
{
    const float* x  = (const float*)d_in[0];
    const float* Wq = (const float*)d_in[1];
    const float* Wk = (const float*)d_in[2];
    const float* Wv = (const float*)d_in[3];
    const float* Wo = (const float*)d_in[4];

    float *q, *k, *v, *ctx;
    cudaGetSymbolAddress((void**)&q,   g_q);
    cudaGetSymbolAddress((void**)&k,   g_k);
    cudaGetSymbolAddress((void**)&v,   g_v);
    cudaGetSymbolAddress((void**)&ctx, g_ctx);

    dim3 gblk(DD / 64, MTOT / 64);  // (16, 128)

    gemm_abt<<<gblk, 256>>>(x, Wq, q, MTOT, DD, DD);
    gemm_abt<<<gblk, 256>>>(x, Wk, k, MTOT, DD, DD);
    gemm_abt<<<gblk, 256>>>(x, Wv, v, MTOT, DD, DD);

    size_t shm = (size_t)(64 * 65 * 2 + 64 * 64) * sizeof(float);  // 49664 B
    cudaFuncSetAttribute(attn_kernel,
                         cudaFuncAttributeMaxDynamicSharedMemorySize, (int)shm);
    attn_kernel<<<dim3(SS / 64, HH, BB), 256, shm>>>(q, k, v, ctx);

    gemm_abt<<<gblk, 256>>>(ctx, Wo, (float*)d_out, MTOT, DD, DD);
}

// round 9
// speedup vs baseline: 2.4339x; 2.4339x over previous
#include <cuda_runtime.h>
#include <cuda_bf16.h>
#include <cstdint>
#include <math.h>

#define BB   4
#define SS   2048
#define DD   1024
#define HH   16
#define DK   64
#define MTOT (BB * SS)

__device__ float g_q[(size_t)MTOT * DD];
__device__ float g_k[(size_t)MTOT * DD];
__device__ float g_v[(size_t)MTOT * DD];
__device__ float g_ctx[(size_t)MTOT * DD];

// ---------------------------------------------------------------------------
// mma.sync m16n8k16 bf16 (fp32 accum) + bf16 hi/lo split helpers
// ---------------------------------------------------------------------------
__device__ __forceinline__ void mma16(float* d,
                                      uint32_t a0, uint32_t a1, uint32_t a2, uint32_t a3,
                                      uint32_t b0, uint32_t b1) {
    asm volatile(
        "mma.sync.aligned.m16n8k16.row.col.f32.bf16.bf16.f32 "
        "{%0,%1,%2,%3},{%4,%5,%6,%7},{%8,%9},{%0,%1,%2,%3};"
        : "+f"(d[0]), "+f"(d[1]), "+f"(d[2]), "+f"(d[3])
        : "r"(a0), "r"(a1), "r"(a2), "r"(a3), "r"(b0), "r"(b1));
}

// pack two fp32 into bf16x2 hi word + bf16x2 lo (residual) word
__device__ __forceinline__ void splitp(float x0, float x1, uint32_t& hi, uint32_t& lo) {
    __nv_bfloat162 h = __floats2bfloat162_rn(x0, x1);
    float f0 = __bfloat162float(h.x), f1 = __bfloat162float(h.y);
    __nv_bfloat162 l = __floats2bfloat162_rn(x0 - f0, x1 - f1);
    hi = *reinterpret_cast<uint32_t*>(&h);
    lo = *reinterpret_cast<uint32_t*>(&l);
}

// ===========================================================================
// GEMM: C[8192,1024] = A[8192,1024] * W[1024,1024]^T (both K-contiguous)
// 128x128 tile, BK=32, 256 threads (8 warps: 4m x 2n), bf16 3-term split.
// ===========================================================================
#define GSTR    20
#define G_AH    0
#define G_AL    2560
#define G_BH    5120
#define G_BL    7680
#define G_STAGE 10240
#define G_SMEM  (2 * G_STAGE * 4)   // 81920 B

__global__ __launch_bounds__(256, 2) void gemm_tc(
    const float* __restrict__ A, const float* __restrict__ B, float* __restrict__ C)
{
    extern __shared__ uint32_t sm[];
    const int tid = threadIdx.x, lane = tid & 31, wid = tid >> 5;
    const int g = lane >> 2, t = lane & 3;
    const int wm = wid & 3, wn = wid >> 2;
    const int row0 = blockIdx.y * 128, col0 = blockIdx.x * 128;

    const float* Ag = A + (size_t)row0 * DD;
    const float* Bg = B + (size_t)col0 * DD;

    float4 ra[4], rb[4];
    float acc[2][8][4];
#pragma unroll
    for (int mb = 0; mb < 2; mb++)
#pragma unroll
        for (int nb = 0; nb < 8; nb++)
#pragma unroll
            for (int i = 0; i < 4; i++) acc[mb][nb][i] = 0.0f;

#define G_LD(kt) do {                                                         \
    _Pragma("unroll")                                                         \
    for (int i = 0; i < 4; i++) {                                             \
        int idx = tid + i * 256, r = idx >> 3, c4 = (idx & 7) * 4;            \
        ra[i] = *(const float4*)(Ag + (size_t)r * DD + (kt) * 32 + c4);       \
        rb[i] = *(const float4*)(Bg + (size_t)r * DD + (kt) * 32 + c4);       \
    } } while (0)

#define G_ST(s) do {                                                          \
    uint32_t* bs = sm + (s) * G_STAGE;                                        \
    _Pragma("unroll")                                                         \
    for (int i = 0; i < 4; i++) {                                             \
        int idx = tid + i * 256, r = idx >> 3, cu = (idx & 7) * 2;            \
        uint32_t h0, l0, h1, l1;                                              \
        splitp(ra[i].x, ra[i].y, h0, l0); splitp(ra[i].z, ra[i].w, h1, l1);   \
        *(uint2*)(bs + G_AH + r * GSTR + cu) = make_uint2(h0, h1);            \
        *(uint2*)(bs + G_AL + r * GSTR + cu) = make_uint2(l0, l1);            \
        splitp(rb[i].x, rb[i].y, h0, l0); splitp(rb[i].z, rb[i].w, h1, l1);   \
        *(uint2*)(bs + G_BH + r * GSTR + cu) = make_uint2(h0, h1);            \
        *(uint2*)(bs + G_BL + r * GSTR + cu) = make_uint2(l0, l1);            \
    } } while (0)

    G_LD(0); G_ST(0); G_LD(1);

    for (int kt = 0; kt < 32; kt++) {
        const int s = kt & 1;
        __syncthreads();
        if (kt + 1 < 32) G_ST((kt + 1) & 1);
        if (kt + 2 < 32) G_LD(kt + 2);

        const uint32_t* st = sm + s * G_STAGE;
#pragma unroll
        for (int ks = 0; ks < 2; ks++) {
            const int ko = ks * 8;
            uint32_t ah[2][4], al[2][4];
#pragma unroll
            for (int mb = 0; mb < 2; mb++) {
                int ab = (wm * 32 + mb * 16 + g) * GSTR + ko + t;
                ah[mb][0] = st[G_AH + ab];            ah[mb][1] = st[G_AH + ab + 8 * GSTR];
                ah[mb][2] = st[G_AH + ab + 4];        ah[mb][3] = st[G_AH + ab + 8 * GSTR + 4];
                al[mb][0] = st[G_AL + ab];            al[mb][1] = st[G_AL + ab + 8 * GSTR];
                al[mb][2] = st[G_AL + ab + 4];        al[mb][3] = st[G_AL + ab + 8 * GSTR + 4];
            }
#pragma unroll
            for (int nb = 0; nb < 8; nb++) {
                int bb = (wn * 64 + nb * 8 + g) * GSTR + ko + t;
                uint32_t bh0 = st[G_BH + bb], bh1 = st[G_BH + bb + 4];
                uint32_t bl0 = st[G_BL + bb], bl1 = st[G_BL + bb + 4];
#pragma unroll
                for (int mb = 0; mb < 2; mb++) {
                    mma16(acc[mb][nb], ah[mb][0], ah[mb][1], ah[mb][2], ah[mb][3], bh0, bh1);
                    mma16(acc[mb][nb], ah[mb][0], ah[mb][1], ah[mb][2], ah[mb][3], bl0, bl1);
                    mma16(acc[mb][nb], al[mb][0], al[mb][1], al[mb][2], al[mb][3], bh0, bh1);
                }
            }
        }
    }

#pragma unroll
    for (int mb = 0; mb < 2; mb++) {
        int r = row0 + wm * 32 + mb * 16 + g;
#pragma unroll
        for (int nb = 0; nb < 8; nb++) {
            int c = col0 + wn * 64 + nb * 8 + 2 * t;
            *(float2*)(C + (size_t)r * DD + c)       = make_float2(acc[mb][nb][0], acc[mb][nb][1]);
            *(float2*)(C + (size_t)(r + 8) * DD + c) = make_float2(acc[mb][nb][2], acc[mb][nb][3]);
        }
    }
}

// ===========================================================================
// Fused flash attention on mma.sync. 64q x 32k tiles, DK=64, 128 threads.
// Warp w owns query rows w*16..w*16+15 end-to-end (softmax warp-private).
// ===========================================================================
#define AQH 0
#define AQL 2304
#define AKH 4608
#define AKL 5760
#define AVH 6912
#define AVL 8064
#define APH 9216
#define APL 10496
#define A_SMEM (11776 * 4)   // 47104 B
#define QSTR 36
#define KSTR 36
#define VSTR 18
#define PSTR 20

__global__ __launch_bounds__(128, 4) void attn_tc(
    const float* __restrict__ q, const float* __restrict__ k,
    const float* __restrict__ v, float* __restrict__ ctx)
{
    extern __shared__ uint32_t sm[];
    __nv_bfloat16* smh = (__nv_bfloat16*)sm;
    const int tid = threadIdx.x, lane = tid & 31, wid = tid >> 5;
    const int g = lane >> 2, t = lane & 3;
    const int b = blockIdx.z, h = blockIdx.y, q0 = blockIdx.x * 64;

    const float* qp    = q + ((size_t)(b * SS) + q0) * DD + h * DK;
    const float* kbase = k + (size_t)(b * SS) * DD + h * DK;
    const float* vbase = v + (size_t)(b * SS) * DD + h * DK;

    // Q planes (scaled by 1/sqrt(64)): 64 rows x 16 float4 = 1024 slots
#pragma unroll
    for (int i = 0; i < 8; i++) {
        int idx = tid + i * 128, r = idx >> 4, c4 = (idx & 15) * 4;
        float4 val = *(const float4*)(qp + (size_t)r * DD + c4);
        uint32_t h0, l0, h1, l1;
        splitp(val.x * 0.125f, val.y * 0.125f, h0, l0);
        splitp(val.z * 0.125f, val.w * 0.125f, h1, l1);
        *(uint2*)(sm + AQH + r * QSTR + c4 / 2) = make_uint2(h0, h1);
        *(uint2*)(sm + AQL + r * QSTR + c4 / 2) = make_uint2(l0, l1);
    }

    float m0 = -1e30f, m1 = -1e30f, l0s = 0.0f, l1s = 0.0f;
    float oacc[8][4];
#pragma unroll
    for (int nb = 0; nb < 8; nb++)
#pragma unroll
        for (int i = 0; i < 4; i++) oacc[nb][i] = 0.0f;

    for (int kt = 0; kt < SS / 32; kt++) {
        const float* kp = kbase + (size_t)(kt * 32) * DD;
        const float* vp = vbase + (size_t)(kt * 32) * DD;
        // K planes [key][dk]: 32 rows x 16 float4 = 512 slots (i < 4 !)
#pragma unroll
        for (int i = 0; i < 4; i++) {
            int idx = tid + i * 128, r = idx >> 4, c4 = (idx & 15) * 4;
            float4 kv = *(const float4*)(kp + (size_t)r * DD + c4);
            uint32_t h0, l0, h1, l1;
            splitp(kv.x, kv.y, h0, l0); splitp(kv.z, kv.w, h1, l1);
            *(uint2*)(sm + AKH + r * KSTR + c4 / 2) = make_uint2(h0, h1);
            *(uint2*)(sm + AKL + r * KSTR + c4 / 2) = make_uint2(l0, l1);
        }
        // V^T planes [dk][key]: 32 keys x 16 float4 = 512 slots (i < 4 !)
#pragma unroll
        for (int i = 0; i < 4; i++) {
            int idx = tid + i * 128, key = idx >> 4, c4 = (idx & 15) * 4;
            float4 vv = *(const float4*)(vp + (size_t)key * DD + c4);
            float e[4] = {vv.x, vv.y, vv.z, vv.w};
#pragma unroll
            for (int j = 0; j < 4; j++) {
                __nv_bfloat16 hb = __float2bfloat16(e[j]);
                __nv_bfloat16 lb = __float2bfloat16(e[j] - __bfloat162float(hb));
                smh[2 * AVH + (c4 + j) * (2 * VSTR) + key] = hb;
                smh[2 * AVL + (c4 + j) * (2 * VSTR) + key] = lb;
            }
        }
        __syncthreads();

        // S[16 x 32] = Q * K^T per warp
        float sacc[4][4];
#pragma unroll
        for (int nb = 0; nb < 4; nb++)
#pragma unroll
            for (int i = 0; i < 4; i++) sacc[nb][i] = 0.0f;
#pragma unroll
        for (int ks = 0; ks < 4; ks++) {
            const int ko = ks * 8;
            int ab = (wid * 16 + g) * QSTR + ko + t;
            uint32_t ah0 = sm[AQH + ab],     ah1 = sm[AQH + ab + 8 * QSTR];
            uint32_t ah2 = sm[AQH + ab + 4], ah3 = sm[AQH + ab + 8 * QSTR + 4];
            uint32_t al0 = sm[AQL + ab],     al1 = sm[AQL + ab + 8 * QSTR];
            uint32_t al2 = sm[AQL + ab + 4], al3 = sm[AQL + ab + 8 * QSTR + 4];
#pragma unroll
            for (int nb = 0; nb < 4; nb++) {
                int bb = (nb * 8 + g) * KSTR + ko + t;
                uint32_t bh0 = sm[AKH + bb], bh1 = sm[AKH + bb + 4];
                uint32_t bl0 = sm[AKL + bb], bl1 = sm[AKL + bb + 4];
                mma16(sacc[nb], ah0, ah1, ah2, ah3, bh0, bh1);
                mma16(sacc[nb], ah0, ah1, ah2, ah3, bl0, bl1);
                mma16(sacc[nb], al0, al1, al2, al3, bh0, bh1);
            }
        }

        // online softmax: row g (comps 0,1), row g+8 (comps 2,3)
        float rm0 = -1e30f, rm1 = -1e30f;
#pragma unroll
        for (int nb = 0; nb < 4; nb++) {
            rm0 = fmaxf(rm0, fmaxf(sacc[nb][0], sacc[nb][1]));
            rm1 = fmaxf(rm1, fmaxf(sacc[nb][2], sacc[nb][3]));
        }
        rm0 = fmaxf(rm0, __shfl_xor_sync(0xffffffffu, rm0, 1));
        rm0 = fmaxf(rm0, __shfl_xor_sync(0xffffffffu, rm0, 2));
        rm1 = fmaxf(rm1, __shfl_xor_sync(0xffffffffu, rm1, 1));
        rm1 = fmaxf(rm1, __shfl_xor_sync(0xffffffffu, rm1, 2));
        float mn0 = fmaxf(m0, rm0), mn1 = fmaxf(m1, rm1);
        float a0 = __expf(m0 - mn0), a1 = __expf(m1 - mn1);
        m0 = mn0; m1 = mn1;
        float ls0 = 0.0f, ls1 = 0.0f;
#pragma unroll
        for (int nb = 0; nb < 4; nb++) {
            float p0 = __expf(sacc[nb][0] - mn0), p1 = __expf(sacc[nb][1] - mn0);
            float p2 = __expf(sacc[nb][2] - mn1), p3 = __expf(sacc[nb][3] - mn1);
            ls0 += p0 + p1; ls1 += p2 + p3;
            uint32_t hi, lo;
            splitp(p0, p1, hi, lo);
            sm[APH + (wid * 16 + g) * PSTR + nb * 4 + t] = hi;
            sm[APL + (wid * 16 + g) * PSTR + nb * 4 + t] = lo;
            splitp(p2, p3, hi, lo);
            sm[APH + (wid * 16 + 8 + g) * PSTR + nb * 4 + t] = hi;
            sm[APL + (wid * 16 + 8 + g) * PSTR + nb * 4 + t] = lo;
        }
        ls0 += __shfl_xor_sync(0xffffffffu, ls0, 1);
        ls0 += __shfl_xor_sync(0xffffffffu, ls0, 2);
        ls1 += __shfl_xor_sync(0xffffffffu, ls1, 1);
        ls1 += __shfl_xor_sync(0xffffffffu, ls1, 2);
        l0s = l0s * a0 + ls0; l1s = l1s * a1 + ls1;
#pragma unroll
        for (int nb = 0; nb < 8; nb++) {
            oacc[nb][0] *= a0; oacc[nb][1] *= a0;
            oacc[nb][2] *= a1; oacc[nb][3] *= a1;
        }
        __syncwarp();

        // O += P * V   (P: A-frag from own rows; V^T: B-frag)
#pragma unroll
        for (int ks = 0; ks < 2; ks++) {
            const int ko = ks * 8;
            int pb = (wid * 16 + g) * PSTR + ko + t;
            uint32_t ph0 = sm[APH + pb],     ph1 = sm[APH + pb + 8 * PSTR];
            uint32_t ph2 = sm[APH + pb + 4], ph3 = sm[APH + pb + 8 * PSTR + 4];
            uint32_t pl0 = sm[APL + pb],     pl1 = sm[APL + pb + 8 * PSTR];
            uint32_t pl2 = sm[APL + pb + 4], pl3 = sm[APL + pb + 8 * PSTR + 4];
#pragma unroll
            for (int nb = 0; nb < 8; nb++) {
                int vb = (nb * 8 + g) * VSTR + ko + t;
                uint32_t vh0 = sm[AVH + vb], vh1 = sm[AVH + vb + 4];
                uint32_t vl0 = sm[AVL + vb], vl1 = sm[AVL + vb + 4];
                mma16(oacc[nb], ph0, ph1, ph2, ph3, vh0, vh1);
                mma16(oacc[nb], ph0, ph1, ph2, ph3, vl0, vl1);
                mma16(oacc[nb], pl0, pl1, pl2, pl3, vh0, vh1);
            }
        }
        __syncthreads();
    }

    const float inv0 = 1.0f / l0s, inv1 = 1.0f / l1s;
    float* op = ctx + ((size_t)(b * SS) + q0) * DD + h * DK;
#pragma unroll
    for (int nb = 0; nb < 8; nb++) {
        int r = wid * 16 + g, c = nb * 8 + 2 * t;
        *(float2*)(op + (size_t)r * DD + c)       = make_float2(oacc[nb][0] * inv0, oacc[nb][1] * inv0);
        *(float2*)(op + (size_t)(r + 8) * DD + c) = make_float2(oacc[nb][2] * inv1, oacc[nb][3] * inv1);
    }
}

// ---------------------------------------------------------------------------
extern "C" void kernel_launch(void* const* d_in, const int* in_sizes, int n_in,
                              void* d_out, int out_size)
{
    const float* x  = (const float*)d_in[0];
    const float* Wq = (const float*)d_in[1];
    const float* Wk = (const float*)d_in[2];
    const float* Wv = (const float*)d_in[3];
    const float* Wo = (const float*)d_in[4];

    float *qv, *kv, *vv, *cv;
    cudaGetSymbolAddress((void**)&qv, g_q);
    cudaGetSymbolAddress((void**)&kv, g_k);
    cudaGetSymbolAddress((void**)&vv, g_v);
    cudaGetSymbolAddress((void**)&cv, g_ctx);

    cudaFuncSetAttribute(gemm_tc, cudaFuncAttributeMaxDynamicSharedMemorySize, G_SMEM);
    cudaFuncSetAttribute(attn_tc, cudaFuncAttributeMaxDynamicSharedMemorySize, A_SMEM);

    dim3 gg(DD / 128, MTOT / 128);   // (8, 64)
    gemm_tc<<<gg, 256, G_SMEM>>>(x, Wq, qv);
    gemm_tc<<<gg, 256, G_SMEM>>>(x, Wk, kv);
    gemm_tc<<<gg, 256, G_SMEM>>>(x, Wv, vv);

    attn_tc<<<dim3(SS / 64, HH, BB), 128, A_SMEM>>>(qv, kv, vv, cv);

    gemm_tc<<<gg, 256, G_SMEM>>>(cv, Wo, (float*)d_out);
}

// round 10
// speedup vs baseline: 3.0009x; 1.2329x over previous
#include <cuda_runtime.h>
#include <cuda_bf16.h>
#include <cstdint>
#include <math.h>

#define BB   4
#define SS   2048
#define DD   1024
#define HH   16
#define DK   64
#define MTOT (BB * SS)

__device__ float g_q[(size_t)MTOT * DD];
__device__ float g_k[(size_t)MTOT * DD];
__device__ float g_v[(size_t)MTOT * DD];
__device__ float g_ctx[(size_t)MTOT * DD];

// ---------------------------------------------------------------------------
// mma.sync m16n8k16 bf16 (fp32 accum) + bf16 hi/lo split helpers
// ---------------------------------------------------------------------------
__device__ __forceinline__ void mma16(float* d,
                                      uint32_t a0, uint32_t a1, uint32_t a2, uint32_t a3,
                                      uint32_t b0, uint32_t b1) {
    asm volatile(
        "mma.sync.aligned.m16n8k16.row.col.f32.bf16.bf16.f32 "
        "{%0,%1,%2,%3},{%4,%5,%6,%7},{%8,%9},{%0,%1,%2,%3};"
        : "+f"(d[0]), "+f"(d[1]), "+f"(d[2]), "+f"(d[3])
        : "r"(a0), "r"(a1), "r"(a2), "r"(a3), "r"(b0), "r"(b1));
}

__device__ __forceinline__ void splitp(float x0, float x1, uint32_t& hi, uint32_t& lo) {
    __nv_bfloat162 h = __floats2bfloat162_rn(x0, x1);
    float f0 = __bfloat162float(h.x), f1 = __bfloat162float(h.y);
    __nv_bfloat162 l = __floats2bfloat162_rn(x0 - f0, x1 - f1);
    hi = *reinterpret_cast<uint32_t*>(&h);
    lo = *reinterpret_cast<uint32_t*>(&l);
}

__device__ __forceinline__ uint32_t smem_u32(const void* p) {
    uint32_t a;
    asm("{ .reg .u64 t; cvta.to.shared.u64 t, %1; cvt.u32.u64 %0, t; }"
        : "=r"(a) : "l"(p));
    return a;
}

__device__ __forceinline__ void ldmx4t(uint32_t& r0, uint32_t& r1,
                                       uint32_t& r2, uint32_t& r3, uint32_t addr) {
    asm volatile("ldmatrix.sync.aligned.m8n8.x4.trans.shared.b16 {%0,%1,%2,%3}, [%4];"
                 : "=r"(r0), "=r"(r1), "=r"(r2), "=r"(r3) : "r"(addr));
}

// ===========================================================================
// GEMM: C[8192,1024] = A[8192,1024] * W[1024,1024]^T  (unchanged from R9)
// ===========================================================================
#define GSTR    20
#define G_AH    0
#define G_AL    2560
#define G_BH    5120
#define G_BL    7680
#define G_STAGE 10240
#define G_SMEM  (2 * G_STAGE * 4)   // 81920 B

__global__ __launch_bounds__(256, 2) void gemm_tc(
    const float* __restrict__ A, const float* __restrict__ B, float* __restrict__ C)
{
    extern __shared__ uint32_t sm[];
    const int tid = threadIdx.x, lane = tid & 31, wid = tid >> 5;
    const int g = lane >> 2, t = lane & 3;
    const int wm = wid & 3, wn = wid >> 2;
    const int row0 = blockIdx.y * 128, col0 = blockIdx.x * 128;

    const float* Ag = A + (size_t)row0 * DD;
    const float* Bg = B + (size_t)col0 * DD;

    float4 ra[4], rb[4];
    float acc[2][8][4];
#pragma unroll
    for (int mb = 0; mb < 2; mb++)
#pragma unroll
        for (int nb = 0; nb < 8; nb++)
#pragma unroll
            for (int i = 0; i < 4; i++) acc[mb][nb][i] = 0.0f;

#define G_LD(kt) do {                                                         \
    _Pragma("unroll")                                                         \
    for (int i = 0; i < 4; i++) {                                             \
        int idx = tid + i * 256, r = idx >> 3, c4 = (idx & 7) * 4;            \
        ra[i] = *(const float4*)(Ag + (size_t)r * DD + (kt) * 32 + c4);       \
        rb[i] = *(const float4*)(Bg + (size_t)r * DD + (kt) * 32 + c4);       \
    } } while (0)

#define G_ST(s) do {                                                          \
    uint32_t* bs = sm + (s) * G_STAGE;                                        \
    _Pragma("unroll")                                                         \
    for (int i = 0; i < 4; i++) {                                             \
        int idx = tid + i * 256, r = idx >> 3, cu = (idx & 7) * 2;            \
        uint32_t h0, l0, h1, l1;                                              \
        splitp(ra[i].x, ra[i].y, h0, l0); splitp(ra[i].z, ra[i].w, h1, l1);   \
        *(uint2*)(bs + G_AH + r * GSTR + cu) = make_uint2(h0, h1);            \
        *(uint2*)(bs + G_AL + r * GSTR + cu) = make_uint2(l0, l1);            \
        splitp(rb[i].x, rb[i].y, h0, l0); splitp(rb[i].z, rb[i].w, h1, l1);   \
        *(uint2*)(bs + G_BH + r * GSTR + cu) = make_uint2(h0, h1);            \
        *(uint2*)(bs + G_BL + r * GSTR + cu) = make_uint2(l0, l1);            \
    } } while (0)

    G_LD(0); G_ST(0); G_LD(1);

    for (int kt = 0; kt < 32; kt++) {
        const int s = kt & 1;
        __syncthreads();
        if (kt + 1 < 32) G_ST((kt + 1) & 1);
        if (kt + 2 < 32) G_LD(kt + 2);

        const uint32_t* st = sm + s * G_STAGE;
#pragma unroll
        for (int ks = 0; ks < 2; ks++) {
            const int ko = ks * 8;
            uint32_t ah[2][4], al[2][4];
#pragma unroll
            for (int mb = 0; mb < 2; mb++) {
                int ab = (wm * 32 + mb * 16 + g) * GSTR + ko + t;
                ah[mb][0] = st[G_AH + ab];            ah[mb][1] = st[G_AH + ab + 8 * GSTR];
                ah[mb][2] = st[G_AH + ab + 4];        ah[mb][3] = st[G_AH + ab + 8 * GSTR + 4];
                al[mb][0] = st[G_AL + ab];            al[mb][1] = st[G_AL + ab + 8 * GSTR];
                al[mb][2] = st[G_AL + ab + 4];        al[mb][3] = st[G_AL + ab + 8 * GSTR + 4];
            }
#pragma unroll
            for (int nb = 0; nb < 8; nb++) {
                int bb = (wn * 64 + nb * 8 + g) * GSTR + ko + t;
                uint32_t bh0 = st[G_BH + bb], bh1 = st[G_BH + bb + 4];
                uint32_t bl0 = st[G_BL + bb], bl1 = st[G_BL + bb + 4];
#pragma unroll
                for (int mb = 0; mb < 2; mb++) {
                    mma16(acc[mb][nb], ah[mb][0], ah[mb][1], ah[mb][2], ah[mb][3], bh0, bh1);
                    mma16(acc[mb][nb], ah[mb][0], ah[mb][1], ah[mb][2], ah[mb][3], bl0, bl1);
                    mma16(acc[mb][nb], al[mb][0], al[mb][1], al[mb][2], al[mb][3], bh0, bh1);
                }
            }
        }
    }

#pragma unroll
    for (int mb = 0; mb < 2; mb++) {
        int r = row0 + wm * 32 + mb * 16 + g;
#pragma unroll
        for (int nb = 0; nb < 8; nb++) {
            int c = col0 + wn * 64 + nb * 8 + 2 * t;
            *(float2*)(C + (size_t)r * DD + c)       = make_float2(acc[mb][nb][0], acc[mb][nb][1]);
            *(float2*)(C + (size_t)(r + 8) * DD + c) = make_float2(acc[mb][nb][2], acc[mb][nb][3]);
        }
    }
}

// ===========================================================================
// Flash attention v2: 128q x 32k tiles, 256 threads (8 warps x 16 q-rows).
// P stays in registers (S C-frag == PV A-frag layout).
// V staged natural [key][dk]; B-frags via ldmatrix.x4.trans.
// smem (u32 offsets): QH 0, QL 4608, KH 9216, KL 10368, VH 11520, VL 12672.
// ===========================================================================
#define AQH 0
#define AQL 4608
#define AKH 9216
#define AKL 10368
#define AVH 11520
#define AVL 12672
#define A_SMEM (13824 * 4)   // 55296 B
#define QSTR 36
#define KSTR 36
#define VSTR 36

__global__ __launch_bounds__(256, 2) void attn_tc(
    const float* __restrict__ q, const float* __restrict__ k,
    const float* __restrict__ v, float* __restrict__ ctx)
{
    extern __shared__ uint32_t sm[];
    const uint32_t sb = smem_u32(sm);
    const int tid = threadIdx.x, lane = tid & 31, wid = tid >> 5;
    const int g = lane >> 2, t = lane & 3;
    const int b = blockIdx.z, h = blockIdx.y, q0 = blockIdx.x * 128;

    const float* qp    = q + ((size_t)(b * SS) + q0) * DD + h * DK;
    const float* kbase = k + (size_t)(b * SS) * DD + h * DK;
    const float* vbase = v + (size_t)(b * SS) * DD + h * DK;

    // Q planes (scaled 0.125): 128 rows x 16 float4 = 2048 slots
#pragma unroll
    for (int i = 0; i < 8; i++) {
        int idx = tid + i * 256, r = idx >> 4, c4 = (idx & 15) * 4;
        float4 val = *(const float4*)(qp + (size_t)r * DD + c4);
        uint32_t h0, l0, h1, l1;
        splitp(val.x * 0.125f, val.y * 0.125f, h0, l0);
        splitp(val.z * 0.125f, val.w * 0.125f, h1, l1);
        *(uint2*)(sm + AQH + r * QSTR + c4 / 2) = make_uint2(h0, h1);
        *(uint2*)(sm + AQL + r * QSTR + c4 / 2) = make_uint2(l0, l1);
    }

    // ldmatrix base address for this lane (depends only on lane)
    // quad q4 = lane>>3 (0..3), lrow = lane&7
    // row(key) = (q4 & 1) * 8 + lrow ; col(dk) = (q4 >> 1) * 8
    const int lrow = lane & 7, q4 = lane >> 3;
    const int lm_row = (q4 & 1) * 8 + lrow;
    const int lm_dk  = (q4 >> 1) * 8;

    float m0 = -1e30f, m1 = -1e30f, l0s = 0.0f, l1s = 0.0f;
    float oacc[8][4];
#pragma unroll
    for (int nb = 0; nb < 8; nb++)
#pragma unroll
        for (int i = 0; i < 4; i++) oacc[nb][i] = 0.0f;

    for (int kt = 0; kt < SS / 32; kt++) {
        const float* kp = kbase + (size_t)(kt * 32) * DD;
        const float* vp = vbase + (size_t)(kt * 32) * DD;
        __syncthreads();   // previous tile's consumers done
        // K + V planes: 32 rows x 16 float4 = 512 slots, 2 per thread each
#pragma unroll
        for (int i = 0; i < 2; i++) {
            int idx = tid + i * 256, r = idx >> 4, c4 = (idx & 15) * 4;
            float4 kv = *(const float4*)(kp + (size_t)r * DD + c4);
            uint32_t h0, l0, h1, l1;
            splitp(kv.x, kv.y, h0, l0); splitp(kv.z, kv.w, h1, l1);
            *(uint2*)(sm + AKH + r * KSTR + c4 / 2) = make_uint2(h0, h1);
            *(uint2*)(sm + AKL + r * KSTR + c4 / 2) = make_uint2(l0, l1);
            float4 vv = *(const float4*)(vp + (size_t)r * DD + c4);
            splitp(vv.x, vv.y, h0, l0); splitp(vv.z, vv.w, h1, l1);
            *(uint2*)(sm + AVH + r * VSTR + c4 / 2) = make_uint2(h0, h1);
            *(uint2*)(sm + AVL + r * VSTR + c4 / 2) = make_uint2(l0, l1);
        }
        __syncthreads();

        // S[16 x 32] = Q * K^T per warp
        float sacc[4][4];
#pragma unroll
        for (int nb = 0; nb < 4; nb++)
#pragma unroll
            for (int i = 0; i < 4; i++) sacc[nb][i] = 0.0f;
#pragma unroll
        for (int ks = 0; ks < 4; ks++) {
            const int ko = ks * 8;
            int ab = (wid * 16 + g) * QSTR + ko + t;
            uint32_t ah0 = sm[AQH + ab],     ah1 = sm[AQH + ab + 8 * QSTR];
            uint32_t ah2 = sm[AQH + ab + 4], ah3 = sm[AQH + ab + 8 * QSTR + 4];
            uint32_t al0 = sm[AQL + ab],     al1 = sm[AQL + ab + 8 * QSTR];
            uint32_t al2 = sm[AQL + ab + 4], al3 = sm[AQL + ab + 8 * QSTR + 4];
#pragma unroll
            for (int nb = 0; nb < 4; nb++) {
                int bb = (nb * 8 + g) * KSTR + ko + t;
                uint32_t bh0 = sm[AKH + bb], bh1 = sm[AKH + bb + 4];
                uint32_t bl0 = sm[AKL + bb], bl1 = sm[AKL + bb + 4];
                mma16(sacc[nb], ah0, ah1, ah2, ah3, bh0, bh1);
                mma16(sacc[nb], ah0, ah1, ah2, ah3, bl0, bl1);
                mma16(sacc[nb], al0, al1, al2, al3, bh0, bh1);
            }
        }

        // online softmax (warp-private; row g -> comps 0,1; row g+8 -> 2,3)
        float rm0 = -1e30f, rm1 = -1e30f;
#pragma unroll
        for (int nb = 0; nb < 4; nb++) {
            rm0 = fmaxf(rm0, fmaxf(sacc[nb][0], sacc[nb][1]));
            rm1 = fmaxf(rm1, fmaxf(sacc[nb][2], sacc[nb][3]));
        }
        rm0 = fmaxf(rm0, __shfl_xor_sync(0xffffffffu, rm0, 1));
        rm0 = fmaxf(rm0, __shfl_xor_sync(0xffffffffu, rm0, 2));
        rm1 = fmaxf(rm1, __shfl_xor_sync(0xffffffffu, rm1, 1));
        rm1 = fmaxf(rm1, __shfl_xor_sync(0xffffffffu, rm1, 2));
        float mn0 = fmaxf(m0, rm0), mn1 = fmaxf(m1, rm1);
        float a0 = __expf(m0 - mn0), a1 = __expf(m1 - mn1);
        m0 = mn0; m1 = mn1;

        // exp + pack P directly into A-fragment words (hi & lo planes)
        float ls0 = 0.0f, ls1 = 0.0f;
        uint32_t pfh[2][4], pfl[2][4];   // [ks][a0..a3]
#pragma unroll
        for (int nb = 0; nb < 4; nb++) {
            float p0 = __expf(sacc[nb][0] - mn0), p1 = __expf(sacc[nb][1] - mn0);
            float p2 = __expf(sacc[nb][2] - mn1), p3 = __expf(sacc[nb][3] - mn1);
            ls0 += p0 + p1; ls1 += p2 + p3;
            const int ks = nb >> 1, half = nb & 1;   // a0/a1 from even nb, a2/a3 from odd
            splitp(p0, p1, pfh[ks][2 * half],     pfl[ks][2 * half]);
            splitp(p2, p3, pfh[ks][2 * half + 1], pfl[ks][2 * half + 1]);
        }
        ls0 += __shfl_xor_sync(0xffffffffu, ls0, 1);
        ls0 += __shfl_xor_sync(0xffffffffu, ls0, 2);
        ls1 += __shfl_xor_sync(0xffffffffu, ls1, 1);
        ls1 += __shfl_xor_sync(0xffffffffu, ls1, 2);
        l0s = l0s * a0 + ls0; l1s = l1s * a1 + ls1;
#pragma unroll
        for (int nb = 0; nb < 8; nb++) {
            oacc[nb][0] *= a0; oacc[nb][1] *= a0;
            oacc[nb][2] *= a1; oacc[nb][3] *= a1;
        }

        // O += P * V : V B-frags via ldmatrix.x4.trans on natural [key][dk]
#pragma unroll
        for (int ks = 0; ks < 2; ks++) {
#pragma unroll
            for (int nbp = 0; nbp < 4; nbp++) {
                const int dk0 = nbp * 16;
                uint32_t off = (uint32_t)((ks * 16 + lm_row) * VSTR + (dk0 + lm_dk) / 2);
                uint32_t vh0, vh1, vh2, vh3, vl0, vl1, vl2, vl3;
                ldmx4t(vh0, vh1, vh2, vh3, sb + 4 * (AVH + off));
                ldmx4t(vl0, vl1, vl2, vl3, sb + 4 * (AVL + off));
                float* d0 = oacc[2 * nbp];
                float* d1 = oacc[2 * nbp + 1];
                mma16(d0, pfh[ks][0], pfh[ks][1], pfh[ks][2], pfh[ks][3], vh0, vh1);
                mma16(d0, pfh[ks][0], pfh[ks][1], pfh[ks][2], pfh[ks][3], vl0, vl1);
                mma16(d0, pfl[ks][0], pfl[ks][1], pfl[ks][2], pfl[ks][3], vh0, vh1);
                mma16(d1, pfh[ks][0], pfh[ks][1], pfh[ks][2], pfh[ks][3], vh2, vh3);
                mma16(d1, pfh[ks][0], pfh[ks][1], pfh[ks][2], pfh[ks][3], vl2, vl3);
                mma16(d1, pfl[ks][0], pfl[ks][1], pfl[ks][2], pfl[ks][3], vh2, vh3);
            }
        }
    }

    const float inv0 = 1.0f / l0s, inv1 = 1.0f / l1s;
    float* op = ctx + ((size_t)(b * SS) + q0) * DD + h * DK;
#pragma unroll
    for (int nb = 0; nb < 8; nb++) {
        int r = wid * 16 + g, c = nb * 8 + 2 * t;
        *(float2*)(op + (size_t)r * DD + c)       = make_float2(oacc[nb][0] * inv0, oacc[nb][1] * inv0);
        *(float2*)(op + (size_t)(r + 8) * DD + c) = make_float2(oacc[nb][2] * inv1, oacc[nb][3] * inv1);
    }
}

// ---------------------------------------------------------------------------
extern "C" void kernel_launch(void* const* d_in, const int* in_sizes, int n_in,
                              void* d_out, int out_size)
{
    const float* x  = (const float*)d_in[0];
    const float* Wq = (const float*)d_in[1];
    const float* Wk = (const float*)d_in[2];
    const float* Wv = (const float*)d_in[3];
    const float* Wo = (const float*)d_in[4];

    float *qv, *kv, *vv, *cv;
    cudaGetSymbolAddress((void**)&qv, g_q);
    cudaGetSymbolAddress((void**)&kv, g_k);
    cudaGetSymbolAddress((void**)&vv, g_v);
    cudaGetSymbolAddress((void**)&cv, g_ctx);

    cudaFuncSetAttribute(gemm_tc, cudaFuncAttributeMaxDynamicSharedMemorySize, G_SMEM);
    cudaFuncSetAttribute(attn_tc, cudaFuncAttributeMaxDynamicSharedMemorySize, A_SMEM);

    dim3 gg(DD / 128, MTOT / 128);   // (8, 64)
    gemm_tc<<<gg, 256, G_SMEM>>>(x, Wq, qv);
    gemm_tc<<<gg, 256, G_SMEM>>>(x, Wk, kv);
    gemm_tc<<<gg, 256, G_SMEM>>>(x, Wv, vv);

    attn_tc<<<dim3(SS / 128, HH, BB), 256, A_SMEM>>>(qv, kv, vv, cv);

    gemm_tc<<<gg, 256, G_SMEM>>>(cv, Wo, (float*)d_out);
}